// round 1
// baseline (speedup 1.0000x reference)
#include <cuda_runtime.h>
#include <math.h>

#define S_LEN 2048
#define B_SZ  256
#define NIN   128
#define H_SZ  256
#define NOUT  128
#define REC_CTAS 64

// 512 MB each: [s][j][b] layout (b contiguous)
__device__ float g_Zx[134217728];
__device__ float g_h [134217728];
__device__ unsigned int g_bar;

__device__ __forceinline__ float gelu_exact(float x){
    return 0.5f * x * (1.0f + erff(x * 0.70710678118654752440f));
}

__global__ void k_init(){ g_bar = 0u; }

// ---------------------------------------------------------------------------
// Kernel A: Zx[s][j][b] = b_ih[j] + sum_{k<128} X[b][s][k] * W_ih[j][k]
// Tile: one s, 64 j x 64 b per CTA, K=128 in two 64-chunks. 256 threads,
// each computes 4j x 4b. X transposed into smem [k][b] (pad 68) for float4 reads.
// ---------------------------------------------------------------------------
__global__ __launch_bounds__(256) void k_zx(const float* __restrict__ X,
                                            const float* __restrict__ Wih,
                                            const float* __restrict__ bih){
    __shared__ float Xs[64][68];
    __shared__ float Ws[64][64];
    const int s  = blockIdx.x;
    const int j0 = blockIdx.y * 64;
    const int b0 = blockIdx.z * 64;
    const int tid = threadIdx.x;
    const int tx = tid & 15, ty = tid >> 4;

    float acc[4][4] = {};
    for (int kc = 0; kc < NIN; kc += 64){
        __syncthreads();
        for (int i = tid; i < 64*64; i += 256){
            int b = i >> 6, k = i & 63;
            Xs[k][b] = X[((size_t)(b0 + b) * S_LEN + s) * NIN + kc + k];
        }
        for (int i = tid; i < 64*64; i += 256){
            int j = i >> 6, k = i & 63;
            Ws[j][k] = Wih[(size_t)(j0 + j) * (NIN + H_SZ) + kc + k];
        }
        __syncthreads();
        #pragma unroll 8
        for (int k = 0; k < 64; ++k){
            float4 xv = *(const float4*)&Xs[k][tx*4];
            #pragma unroll
            for (int jj = 0; jj < 4; ++jj){
                float w = Ws[ty*4 + jj][k];
                acc[jj][0] += w * xv.x;  acc[jj][1] += w * xv.y;
                acc[jj][2] += w * xv.z;  acc[jj][3] += w * xv.w;
            }
        }
    }
    #pragma unroll
    for (int jj = 0; jj < 4; ++jj){
        int j = j0 + ty*4 + jj;
        float bb = bih[j];
        float4 o;
        o.x = acc[jj][0] + bb; o.y = acc[jj][1] + bb;
        o.z = acc[jj][2] + bb; o.w = acc[jj][3] + bb;
        *(float4*)&g_Zx[((size_t)s * H_SZ + j) * B_SZ + b0 + tx*4] = o;
    }
}

// ---------------------------------------------------------------------------
// Kernel B: persistent recurrent spine. 64 CTAs x 256 threads.
// CTA owns 4 H-columns (all 256 batch rows -> BN fully local).
// thread = batch index b. W_h slice (4x256) resident in smem for all steps.
// One grid barrier per step (monotonic counter in gmem).
// ---------------------------------------------------------------------------
__global__ __launch_bounds__(256) void k_rec(const float* __restrict__ Wih,
                                             const float* __restrict__ gamma,
                                             const float* __restrict__ beta){
    __shared__ float Wsm[H_SZ * 4];   // [k][jj] = W_ih[j0+jj][128+k]
    __shared__ float redsm[8][8];     // per-warp partial sums (4 sum, 4 sumsq)
    __shared__ float bns[8];          // scale[4], shift[4]

    const int tid = threadIdx.x;
    const int j0  = blockIdx.x * 4;
    const int lane = tid & 31, warp = tid >> 5;

    for (int i = tid; i < H_SZ * 4; i += 256){
        int k = i >> 2, jj = i & 3;
        Wsm[i] = Wih[(size_t)(j0 + jj) * (NIN + H_SZ) + NIN + k];
    }
    __syncthreads();

    for (int s = 0; s < S_LEN; ++s){
        const float* zx = g_Zx + ((size_t)s * H_SZ + j0) * B_SZ + tid;
        float a0 = zx[0], a1 = zx[256], a2 = zx[512], a3 = zx[768];

        if (s > 0){
            const float* hp = g_h + (size_t)(s-1) * H_SZ * B_SZ + tid;
            #pragma unroll 16
            for (int k = 0; k < H_SZ; ++k){
                float hv = __ldcg(hp + k * B_SZ);          // coalesced, L2
                float4 wv = *(const float4*)&Wsm[k*4];     // uniform broadcast
                a0 += hv * wv.x; a1 += hv * wv.y;
                a2 += hv * wv.z; a3 += hv * wv.w;
            }
        }

        // BatchNorm stats over the 256 threads (= batch axis), per column jj
        float s10=a0, s11=a1, s12=a2, s13=a3;
        float s20=a0*a0, s21=a1*a1, s22=a2*a2, s23=a3*a3;
        #pragma unroll
        for (int off = 16; off; off >>= 1){
            s10 += __shfl_down_sync(0xffffffffu, s10, off);
            s11 += __shfl_down_sync(0xffffffffu, s11, off);
            s12 += __shfl_down_sync(0xffffffffu, s12, off);
            s13 += __shfl_down_sync(0xffffffffu, s13, off);
            s20 += __shfl_down_sync(0xffffffffu, s20, off);
            s21 += __shfl_down_sync(0xffffffffu, s21, off);
            s22 += __shfl_down_sync(0xffffffffu, s22, off);
            s23 += __shfl_down_sync(0xffffffffu, s23, off);
        }
        if (lane == 0){
            redsm[warp][0]=s10; redsm[warp][1]=s11; redsm[warp][2]=s12; redsm[warp][3]=s13;
            redsm[warp][4]=s20; redsm[warp][5]=s21; redsm[warp][6]=s22; redsm[warp][7]=s23;
        }
        __syncthreads();
        if (tid < 4){
            float S1 = 0.f, S2 = 0.f;
            #pragma unroll
            for (int w = 0; w < 8; ++w){ S1 += redsm[w][tid]; S2 += redsm[w][4+tid]; }
            float mu  = S1 * (1.0f/256.0f);
            float var = S2 * (1.0f/256.0f) - mu*mu;
            float rs  = rsqrtf(var + 1e-5f);
            float sc  = rs * gamma[j0 + tid];
            bns[tid]     = sc;
            bns[4 + tid] = beta[j0 + tid] - mu * sc;
        }
        __syncthreads();

        float h0 = gelu_exact(a0*bns[0] + bns[4]);
        float h1 = gelu_exact(a1*bns[1] + bns[5]);
        float h2 = gelu_exact(a2*bns[2] + bns[6]);
        float h3 = gelu_exact(a3*bns[3] + bns[7]);

        float* hw = g_h + ((size_t)s * H_SZ + j0) * B_SZ + tid;
        __stcg(hw,       h0);
        __stcg(hw + 256, h1);
        __stcg(hw + 512, h2);
        __stcg(hw + 768, h3);

        // grid barrier: all CTAs' h(s) visible before any CTA starts step s+1
        __threadfence();
        __syncthreads();
        if (tid == 0){
            atomicAdd(&g_bar, 1u);
            unsigned target = (unsigned)REC_CTAS * (unsigned)(s + 1);
            volatile unsigned int* bp = &g_bar;
            while (*bp < target) { }
            __threadfence();
        }
        __syncthreads();
    }
}

// ---------------------------------------------------------------------------
// Kernel C: out[b][s][o] = gelu( sum_k g_h[s][k][b] * W_ho[o][k] + b_ho[o] )
// Tile: one s, 64 o x 64 b per CTA, K=256 in four 64-chunks.
// g_h is already [k][b] -> no transpose needed for float4 smem reads.
// ---------------------------------------------------------------------------
__global__ __launch_bounds__(256) void k_out(const float* __restrict__ Who,
                                             const float* __restrict__ bho,
                                             float* __restrict__ out){
    __shared__ float Hs[64][68];
    __shared__ float Ws[64][64];
    const int s  = blockIdx.x;
    const int o0 = blockIdx.y * 64;
    const int b0 = blockIdx.z * 64;
    const int tid = threadIdx.x;
    const int tx = tid & 15, ty = tid >> 4;

    float acc[4][4] = {};   // [jj over o][ii over b]
    for (int kc = 0; kc < H_SZ; kc += 64){
        __syncthreads();
        for (int i = tid; i < 64*64; i += 256){
            int k = i >> 6, b = i & 63;
            Hs[k][b] = g_h[((size_t)s * H_SZ + kc + k) * B_SZ + b0 + b];
        }
        for (int i = tid; i < 64*64; i += 256){
            int o = i >> 6, k = i & 63;
            Ws[o][k] = Who[(size_t)(o0 + o) * H_SZ + kc + k];
        }
        __syncthreads();
        #pragma unroll 8
        for (int k = 0; k < 64; ++k){
            float4 hv = *(const float4*)&Hs[k][tx*4];
            #pragma unroll
            for (int jj = 0; jj < 4; ++jj){
                float w = Ws[ty*4 + jj][k];
                acc[jj][0] += w * hv.x;  acc[jj][1] += w * hv.y;
                acc[jj][2] += w * hv.z;  acc[jj][3] += w * hv.w;
            }
        }
    }
    float bb[4];
    #pragma unroll
    for (int jj = 0; jj < 4; ++jj) bb[jj] = bho[o0 + ty*4 + jj];
    #pragma unroll
    for (int ii = 0; ii < 4; ++ii){
        float4 r;
        r.x = gelu_exact(acc[0][ii] + bb[0]);
        r.y = gelu_exact(acc[1][ii] + bb[1]);
        r.z = gelu_exact(acc[2][ii] + bb[2]);
        r.w = gelu_exact(acc[3][ii] + bb[3]);
        size_t idx = ((size_t)(b0 + tx*4 + ii) * S_LEN + s) * NOUT + o0 + ty*4;
        *(float4*)&out[idx] = r;
    }
}

// ---------------------------------------------------------------------------
extern "C" void kernel_launch(void* const* d_in, const int* in_sizes, int n_in,
                              void* d_out, int out_size) {
    const float* X     = (const float*)d_in[0];
    const float* Wih   = (const float*)d_in[1];
    const float* bih   = (const float*)d_in[2];
    const float* Who   = (const float*)d_in[3];
    const float* bho   = (const float*)d_in[4];
    const float* gamma = (const float*)d_in[5];
    const float* beta  = (const float*)d_in[6];
    float* out = (float*)d_out;

    k_init<<<1, 1>>>();
    k_zx <<<dim3(S_LEN, H_SZ/64, B_SZ/64), 256>>>(X, Wih, bih);
    k_rec<<<REC_CTAS, 256>>>(Wih, gamma, beta);
    k_out<<<dim3(S_LEN, NOUT/64, B_SZ/64), 256>>>(Who, bho, out);
}